// round 14
// baseline (speedup 1.0000x reference)
#include <cuda_runtime.h>
#include <cuda_fp16.h>
#include <math.h>
#include <stdint.h>

// ---------------- scratch (static device globals; no allocation) ----------------
__device__ __half  g_msgh[4096 * 64];
__device__ __half  g_w1t [256 * 64];
__device__ __half  g_w2t [512 * 256];
__device__ __half  g_w3t [4096 * 512];
__device__ __half  g_fw1t[128 * 64];
__device__ __half  g_fw2t[256 * 128];
__device__ __half  g_h1  [4096 * 256];
__device__ __half  g_h2  [4096 * 512];
__device__ __half  g_S   [4096u * 4096u];
__device__ __half  g_f   [4096 * 128];
__device__ __half  g_FL  [4096 * 256];

// ---------------- helpers ----------------
__device__ __forceinline__ uint32_t smem_u32(const void* p) {
    uint32_t a;
    asm("{ .reg .u64 t; cvta.to.shared.u64 t, %1; cvt.u32.u64 %0, t; }" : "=r"(a) : "l"(p));
    return a;
}
__device__ __forceinline__ void cp_async16(uint32_t dst, const void* src) {
    asm volatile("cp.async.cg.shared.global [%0], [%1], 16;" :: "r"(dst), "l"(src));
}
#define CP_COMMIT() asm volatile("cp.async.commit_group;" ::: "memory")

__device__ __forceinline__ void ldsm_x4(uint32_t (&r)[4], uint32_t addr) {
    asm volatile("ldmatrix.sync.aligned.m8n8.x4.shared.b16 {%0,%1,%2,%3}, [%4];"
                 : "=r"(r[0]), "=r"(r[1]), "=r"(r[2]), "=r"(r[3]) : "r"(addr));
}
__device__ __forceinline__ void mma16816h(float (&d)[4], const uint32_t (&a)[4],
                                          uint32_t b0, uint32_t b1) {
    asm volatile(
        "mma.sync.aligned.m16n8k16.row.col.f32.f16.f16.f32 "
        "{%0,%1,%2,%3}, {%4,%5,%6,%7}, {%8,%9}, {%0,%1,%2,%3};"
        : "+f"(d[0]), "+f"(d[1]), "+f"(d[2]), "+f"(d[3])
        : "r"(a[0]), "r"(a[1]), "r"(a[2]), "r"(a[3]), "r"(b0), "r"(b1));
}

// ---------------- fp32 -> fp16 elementwise ----------------
__global__ __launch_bounds__(256) void f32_to_f16(
    const float* __restrict__ x, __half* __restrict__ y)
{
    int i = blockIdx.x * 256 + threadIdx.x;
    float2 v = reinterpret_cast<const float2*>(x)[i];
    reinterpret_cast<__half2*>(y)[i] = __floats2half2_rn(v.x, v.y);
}

// W [K,N] f32 -> W^T fp16 [N,K]; 64k x 32n tiles, half2 stores.
__global__ __launch_bounds__(256) void transpose_h16(
    const float* __restrict__ W, __half* __restrict__ T, int K, int N)
{
    __shared__ float t[64][33];
    int tx = threadIdx.x, ty = threadIdx.y;       // 32 x 8
    int bx = blockIdx.x, by = blockIdx.y;         // N/32, K/64
    #pragma unroll
    for (int i = 0; i < 8; i++) {
        int k = by * 64 + ty + i * 8;
        t[ty + i * 8][tx] = W[(size_t)k * N + bx * 32 + tx];
    }
    __syncthreads();
    #pragma unroll
    for (int i = 0; i < 4; i++) {
        int nl = ty + i * 8;
        int n  = bx * 32 + nl;
        __half2 v = __floats2half2_rn(t[2 * tx][nl], t[2 * tx + 1][nl]);
        *reinterpret_cast<__half2*>(&T[(size_t)n * K + by * 64 + 2 * tx]) = v;
    }
}

// ---------------- generic fp16 tensor GEMM: C = act(A @ Bt^T + bias) ----------------
// m_off: tile_m offset (row-slab pipelining of the big GEMM).
template <int ACT>  // 0 = relu, 1 = tanh
__global__ __launch_bounds__(256, 2) void gemmT_h16(
    const __half* __restrict__ A, const __half* __restrict__ Bt,
    const float* __restrict__ bias, __half* __restrict__ C,
    int K, int N, int nch, int m_off)
{
    extern __shared__ char dynsmem[];
    const uint32_t sbase = smem_u32(dynsmem);

    const int tid  = threadIdx.x;
    const int lane = tid & 31;
    const int wid  = tid >> 5;
    const int wm   = wid & 3;
    const int wn   = wid >> 2;
    const int tile_n = blockIdx.x, tile_m = blockIdx.y + m_off;

    auto load_chunk = [&](int stage, int kc) {
        const uint32_t st = sbase + stage * 32768;
        #pragma unroll
        for (int it = 0; it < 8; it++) {
            int u   = tid + it * 256;
            int buf = u >> 10;
            int idx = u & 1023;
            int row = idx >> 3;
            int c   = idx & 7;
            uint32_t dst = st + buf * 16384 + row * 128 + ((c ^ (row & 7)) << 4);
            const __half* src = buf ? Bt : A;
            int grow = (buf ? tile_n : tile_m) * 128 + row;
            cp_async16(dst, (const char*)src + ((size_t)grow * K + kc * 64 + c * 8) * 2);
        }
        CP_COMMIT();
    };

    float acc[2][8][4];
    #pragma unroll
    for (int i = 0; i < 2; i++)
        #pragma unroll
        for (int j = 0; j < 8; j++)
            #pragma unroll
            for (int t = 0; t < 4; t++) acc[i][j][t] = 0.0f;

    load_chunk(0, 0);
    if (nch > 1) load_chunk(1, 1);

    const int a_row_in = (lane & 15);
    const int a_cb_add = (lane >> 4);
    const int b_row_in = ((lane >> 4) << 3) + (lane & 7);
    const int b_cb_add = (lane >> 3) & 1;

    for (int c = 0; c < nch; ++c) {
        if (c < nch - 1) asm volatile("cp.async.wait_group 1;" ::: "memory");
        else             asm volatile("cp.async.wait_group 0;" ::: "memory");
        __syncthreads();
        if (c + 2 < nch) load_chunk((c + 2) % 3, c + 2);

        const uint32_t aB = sbase + (c % 3) * 32768;
        const uint32_t bB = aB + 16384;

        #pragma unroll
        for (int kk = 0; kk < 4; kk++) {
            const int cb = kk * 2;
            uint32_t ah[2][4];
            #pragma unroll
            for (int mi = 0; mi < 2; mi++) {
                int row = wm * 32 + mi * 16 + a_row_in;
                uint32_t off = row * 128 + (((cb + a_cb_add) ^ (row & 7)) << 4);
                ldsm_x4(ah[mi], aB + off);
            }
            uint32_t bh[4][4];
            #pragma unroll
            for (int nq = 0; nq < 4; nq++) {
                int row = wn * 64 + nq * 16 + b_row_in;
                uint32_t off = row * 128 + (((cb + b_cb_add) ^ (row & 7)) << 4);
                ldsm_x4(bh[nq], bB + off);
            }
            #pragma unroll
            for (int nq = 0; nq < 4; nq++)
                #pragma unroll
                for (int mi = 0; mi < 2; mi++) {
                    mma16816h(acc[mi][2 * nq],     ah[mi], bh[nq][0], bh[nq][1]);
                    mma16816h(acc[mi][2 * nq + 1], ah[mi], bh[nq][2], bh[nq][3]);
                }
        }
    }

    const int col0 = tile_n * 128 + wn * 64 + (lane & 3) * 2;
    #pragma unroll
    for (int mi = 0; mi < 2; mi++) {
        int r0 = tile_m * 128 + wm * 32 + mi * 16 + (lane >> 2);
        #pragma unroll
        for (int nb = 0; nb < 8; nb++) {
            int col = col0 + nb * 8;
            float b0 = __ldg(bias + col), b1 = __ldg(bias + col + 1);
            float v0 = acc[mi][nb][0] + b0, v1 = acc[mi][nb][1] + b1;
            float v2 = acc[mi][nb][2] + b0, v3 = acc[mi][nb][3] + b1;
            if (ACT == 0) {
                v0 = fmaxf(v0, 0.f); v1 = fmaxf(v1, 0.f);
                v2 = fmaxf(v2, 0.f); v3 = fmaxf(v3, 0.f);
            } else {
                v0 = tanhf(v0); v1 = tanhf(v1);
                v2 = tanhf(v2); v3 = tanhf(v3);
            }
            *reinterpret_cast<__half2*>(C + (size_t)r0 * N + col) = __floats2half2_rn(v0, v1);
            *reinterpret_cast<__half2*>(C + (size_t)(r0 + 8) * N + col) = __floats2half2_rn(v2, v3);
        }
    }
}

// ---------------- shared conv core (single-sync, register conv) ----------------
__device__ __forceinline__ void conv_and_store(
    const float* __restrict__ img, const float* __restrict__ g,
    float* __restrict__ outc, int tid)
{
    const int r0 = (tid >> 4) << 2;
    const int c0 = (tid & 15) << 2;

    float h[8][4];
    #pragma unroll
    for (int i = 0; i < 8; i++) {
        int r = r0 - 2 + i;
        if (r >= 0 && r < 64) {
            const float* ir = &img[r << 6];
            float x[12];
            if (c0 > 0) {
                float4 v = *reinterpret_cast<const float4*>(ir + c0 - 4);
                x[0] = v.x; x[1] = v.y; x[2] = v.z; x[3] = v.w;
            } else { x[0] = x[1] = x[2] = x[3] = 0.0f; }
            {
                float4 v = *reinterpret_cast<const float4*>(ir + c0);
                x[4] = v.x; x[5] = v.y; x[6] = v.z; x[7] = v.w;
            }
            if (c0 < 60) {
                float4 v = *reinterpret_cast<const float4*>(ir + c0 + 4);
                x[8] = v.x; x[9] = v.y; x[10] = v.z; x[11] = v.w;
            } else { x[8] = x[9] = x[10] = x[11] = 0.0f; }
            #pragma unroll
            for (int j = 0; j < 4; j++)
                h[i][j] = g[0]*x[j+2] + g[1]*x[j+3] + g[2]*x[j+4] + g[3]*x[j+5] + g[4]*x[j+6];
        } else {
            #pragma unroll
            for (int j = 0; j < 4; j++) h[i][j] = 0.0f;
        }
    }

    #pragma unroll
    for (int i = 0; i < 4; i++) {
        float4 o;
        o.x = g[0]*h[i][0] + g[1]*h[i+1][0] + g[2]*h[i+2][0] + g[3]*h[i+3][0] + g[4]*h[i+4][0];
        o.y = g[0]*h[i][1] + g[1]*h[i+1][1] + g[2]*h[i+2][1] + g[3]*h[i+3][1] + g[4]*h[i+4][1];
        o.z = g[0]*h[i][2] + g[1]*h[i+1][2] + g[2]*h[i+2][2] + g[3]*h[i+3][2] + g[4]*h[i+4][2];
        o.w = g[0]*h[i][3] + g[1]*h[i+1][3] + g[2]*h[i+2][3] + g[3]*h[i+3][3] + g[4]*h[i+4][3];
        *reinterpret_cast<float4*>(outc + ((r0 + i) << 6) + c0) = o;
    }
}

__device__ __forceinline__ void gauss5(float* g) {
    float s = 0.0f;
    #pragma unroll
    for (int i = 0; i < 5; i++) {
        float c = (float)(i - 2);
        g[i] = expf(-c * c * 0.5f);
        s += g[i];
    }
    #pragma unroll
    for (int i = 0; i < 5; i++) g[i] /= s;
}

// ---- channel 0 (spatial, needs S); b_off = batch slab offset ----
__global__ __launch_bounds__(256) void assemble_ch0(
    const __half* __restrict__ S, float* __restrict__ out, int b_off)
{
    __shared__ float img[64 * 64];
    const int b = blockIdx.x + b_off, tid = threadIdx.x;
    float g[5]; gauss5(g);

    const uint4* S4 = reinterpret_cast<const uint4*>(S + (size_t)b * 4096);
    #pragma unroll
    for (int it = 0; it < 2; it++) {
        int i = tid + it * 256;
        uint4 u = S4[i];
        const __half2* hp = reinterpret_cast<const __half2*>(&u);
        float* d = &img[i << 3];
        #pragma unroll
        for (int j = 0; j < 4; j++) {
            float2 f = __half22float2(hp[j]);
            d[2 * j] = f.x; d[2 * j + 1] = f.y;
        }
    }
    __syncthreads();
    conv_and_store(img, g, out + (size_t)b * 3 * 4096, tid);
}

// ---- channels 1,2 (freq/block; independent of S) ----
__global__ __launch_bounds__(256) void assemble_ch12(
    const __half* __restrict__ FL, const float* __restrict__ msg,
    float* __restrict__ out)
{
    __shared__ float img[64 * 64];
    __shared__ float fl[256];
    const int b = blockIdx.x, ch = blockIdx.y + 1, tid = threadIdx.x;
    float g[5]; gauss5(g);

    if (ch == 1) {
        fl[tid] = __half2float(FL[(size_t)b * 256 + tid]);
        __syncthreads();
        #pragma unroll
        for (int it = 0; it < 16; it++) {
            int idx = tid + it * 256;
            int p = idx >> 6, q = idx & 63;
            float pp = (float)(p * 15) / 63.0f;
            float pq = (float)(q * 15) / 63.0f;
            int lp = (int)pp, lq = (int)pq;
            float wp = pp - (float)lp, wq = pq - (float)lq;
            int hp = min(lp + 1, 15), hq = min(lq + 1, 15);
            float v00 = fl[lp * 16 + lq], v01 = fl[lp * 16 + hq];
            float v10 = fl[hp * 16 + lq], v11 = fl[hp * 16 + hq];
            float top = (1.0f - wq) * v00 + wq * v01;
            float bot = (1.0f - wq) * v10 + wq * v11;
            img[idx] = (1.0f - wp) * top + wp * bot;
        }
    } else {
        if (tid < 64) fl[tid] = msg[(size_t)b * 64 + tid];
        __syncthreads();
        #pragma unroll
        for (int it = 0; it < 16; it++) {
            int idx = tid + it * 256;
            int p = idx >> 6, q = idx & 63;
            img[idx] = fl[((p >> 3) << 3) + (q >> 3)];
        }
    }
    __syncthreads();
    conv_and_store(img, g, out + ((size_t)b * 3 + ch) * 4096, tid);
}

// ---------------- launch (fork-join + gemm3/ch0 slab pipeline) ----------------
extern "C" void kernel_launch(void* const* d_in, const int* in_sizes, int n_in,
                              void* d_out, int out_size)
{
    const float* msg = (const float*)d_in[0];
    const float* sW1 = (const float*)d_in[1];
    const float* sb1 = (const float*)d_in[2];
    const float* sW2 = (const float*)d_in[3];
    const float* sb2 = (const float*)d_in[4];
    const float* sW3 = (const float*)d_in[5];
    const float* sb3 = (const float*)d_in[6];
    const float* fW1 = (const float*)d_in[7];
    const float* fb1 = (const float*)d_in[8];
    const float* fW2 = (const float*)d_in[9];
    const float* fb2 = (const float*)d_in[10];
    float* out = (float*)d_out;

    __half *msgh, *w1t, *w2t, *w3t, *fw1t, *fw2t, *h1, *h2, *S, *f, *FL;
    cudaGetSymbolAddress((void**)&msgh, g_msgh);
    cudaGetSymbolAddress((void**)&w1t,  g_w1t);
    cudaGetSymbolAddress((void**)&w2t,  g_w2t);
    cudaGetSymbolAddress((void**)&w3t,  g_w3t);
    cudaGetSymbolAddress((void**)&fw1t, g_fw1t);
    cudaGetSymbolAddress((void**)&fw2t, g_fw2t);
    cudaGetSymbolAddress((void**)&h1,   g_h1);
    cudaGetSymbolAddress((void**)&h2,   g_h2);
    cudaGetSymbolAddress((void**)&S,    g_S);
    cudaGetSymbolAddress((void**)&f,    g_f);
    cudaGetSymbolAddress((void**)&FL,   g_FL);

    cudaFuncSetAttribute(gemmT_h16<0>, cudaFuncAttributeMaxDynamicSharedMemorySize, 98304);
    cudaFuncSetAttribute(gemmT_h16<1>, cudaFuncAttributeMaxDynamicSharedMemorySize, 98304);

    constexpr int NSLAB = 4;                 // 8 tile_m rows (1024 batches) per slab
    static cudaStream_t s1 = nullptr, s2 = nullptr, s3 = nullptr;
    static cudaEvent_t evFork = nullptr, evW12 = nullptr, evW3 = nullptr,
                       ev2 = nullptr, ev3 = nullptr, evSlab[NSLAB] = {};
    if (s1 == nullptr) {
        cudaStreamCreateWithFlags(&s1, cudaStreamNonBlocking);
        cudaStreamCreateWithFlags(&s2, cudaStreamNonBlocking);
        cudaStreamCreateWithFlags(&s3, cudaStreamNonBlocking);
        cudaEventCreateWithFlags(&evFork, cudaEventDisableTiming);
        cudaEventCreateWithFlags(&evW12, cudaEventDisableTiming);
        cudaEventCreateWithFlags(&evW3, cudaEventDisableTiming);
        cudaEventCreateWithFlags(&ev2, cudaEventDisableTiming);
        cudaEventCreateWithFlags(&ev3, cudaEventDisableTiming);
        for (int i = 0; i < NSLAB; i++)
            cudaEventCreateWithFlags(&evSlab[i], cudaEventDisableTiming);
    }

    // main: msg convert; fork
    f32_to_f16<<<4096 * 64 / 512, 256>>>(msg, msgh);
    cudaEventRecord(evFork, 0);
    cudaStreamWaitEvent(s1, evFork, 0);
    cudaStreamWaitEvent(s2, evFork, 0);

    // s1: w2t then w3t transposes (off critical path)
    transpose_h16<<<dim3(512 / 32, 256 / 64), dim3(32, 8), 0, s1>>>(sW2, w2t, 256, 512);
    cudaEventRecord(evW12, s1);
    transpose_h16<<<dim3(4096 / 32, 512 / 64), dim3(32, 8), 0, s1>>>(sW3, w3t, 512, 4096);
    cudaEventRecord(evW3, s1);

    // s2: freq chain + channels 1,2
    transpose_h16<<<dim3(128 / 32, 64 / 64),  dim3(32, 8), 0, s2>>>(fW1, fw1t, 64, 128);
    transpose_h16<<<dim3(256 / 32, 128 / 64), dim3(32, 8), 0, s2>>>(fW2, fw2t, 128, 256);
    gemmT_h16<0><<<dim3(1, 32), 256, 98304, s2>>>(msgh, fw1t, fb1, f,  64, 128, 1, 0);
    gemmT_h16<1><<<dim3(2, 32), 256, 98304, s2>>>(f,    fw2t, fb2, FL, 128, 256, 2, 0);
    assemble_ch12<<<dim3(4096, 2), 256, 0, s2>>>(FL, msg, out);
    cudaEventRecord(ev2, s2);

    // main: spatial chain
    transpose_h16<<<dim3(256 / 32, 64 / 64), dim3(32, 8)>>>(sW1, w1t, 64, 256);
    gemmT_h16<0><<<dim3(2, 32), 256, 98304>>>(msgh, w1t, sb1, h1, 64, 256, 1, 0);
    cudaStreamWaitEvent(0, evW12, 0);
    gemmT_h16<0><<<dim3(4, 32), 256, 98304>>>(h1, w2t, sb2, h2, 256, 512, 4, 0);
    cudaStreamWaitEvent(0, evW3, 0);

    // gemm3 in row-slabs, ch0 pipelined on s3
    for (int i = 0; i < NSLAB; i++) {
        gemmT_h16<1><<<dim3(32, 32 / NSLAB), 256, 98304>>>(
            h2, w3t, sb3, S, 512, 4096, 8, i * (32 / NSLAB));
        cudaEventRecord(evSlab[i], 0);
        cudaStreamWaitEvent(s3, evSlab[i], 0);
        assemble_ch0<<<4096 / NSLAB, 256, 0, s3>>>(S, out, i * (4096 / NSLAB));
    }
    cudaEventRecord(ev3, s3);

    // join
    cudaStreamWaitEvent(0, ev2, 0);
    cudaStreamWaitEvent(0, ev3, 0);
}

// round 15
// speedup vs baseline: 1.1037x; 1.1037x over previous
#include <cuda_runtime.h>
#include <cuda_fp16.h>
#include <math.h>
#include <stdint.h>

// ---------------- scratch (static device globals; no allocation) ----------------
__device__ __half  g_msgh[4096 * 64];
__device__ __half  g_w1t [256 * 64];
__device__ __half  g_w2t [512 * 256];
__device__ __half  g_w3t [4096 * 512];
__device__ __half  g_fw1t[128 * 64];
__device__ __half  g_fw2t[256 * 128];
__device__ __half  g_h1  [4096 * 256];
__device__ __half  g_h2  [4096 * 512];
__device__ __half  g_S   [4096u * 4096u];
__device__ __half  g_f   [4096 * 128];
__device__ __half  g_FL  [4096 * 256];

// ---------------- helpers ----------------
__device__ __forceinline__ uint32_t smem_u32(const void* p) {
    uint32_t a;
    asm("{ .reg .u64 t; cvta.to.shared.u64 t, %1; cvt.u32.u64 %0, t; }" : "=r"(a) : "l"(p));
    return a;
}
__device__ __forceinline__ void cp_async16(uint32_t dst, const void* src) {
    asm volatile("cp.async.cg.shared.global [%0], [%1], 16;" :: "r"(dst), "l"(src));
}
#define CP_COMMIT() asm volatile("cp.async.commit_group;" ::: "memory")

__device__ __forceinline__ void ldsm_x4(uint32_t (&r)[4], uint32_t addr) {
    asm volatile("ldmatrix.sync.aligned.m8n8.x4.shared.b16 {%0,%1,%2,%3}, [%4];"
                 : "=r"(r[0]), "=r"(r[1]), "=r"(r[2]), "=r"(r[3]) : "r"(addr));
}
__device__ __forceinline__ void mma16816h(float (&d)[4], const uint32_t (&a)[4],
                                          uint32_t b0, uint32_t b1) {
    asm volatile(
        "mma.sync.aligned.m16n8k16.row.col.f32.f16.f16.f32 "
        "{%0,%1,%2,%3}, {%4,%5,%6,%7}, {%8,%9}, {%0,%1,%2,%3};"
        : "+f"(d[0]), "+f"(d[1]), "+f"(d[2]), "+f"(d[3])
        : "r"(a[0]), "r"(a[1]), "r"(a[2]), "r"(a[3]), "r"(b0), "r"(b1));
}

// ---------------- fp32 -> fp16 elementwise ----------------
__global__ __launch_bounds__(256) void f32_to_f16(
    const float* __restrict__ x, __half* __restrict__ y)
{
    int i = blockIdx.x * 256 + threadIdx.x;
    float2 v = reinterpret_cast<const float2*>(x)[i];
    reinterpret_cast<__half2*>(y)[i] = __floats2half2_rn(v.x, v.y);
}

// W [K,N] f32 -> W^T fp16 [N,K]; 64k x 32n tiles, half2 stores.
__global__ __launch_bounds__(256) void transpose_h16(
    const float* __restrict__ W, __half* __restrict__ T, int K, int N)
{
    __shared__ float t[64][33];
    int tx = threadIdx.x, ty = threadIdx.y;       // 32 x 8
    int bx = blockIdx.x, by = blockIdx.y;         // N/32, K/64
    #pragma unroll
    for (int i = 0; i < 8; i++) {
        int k = by * 64 + ty + i * 8;
        t[ty + i * 8][tx] = W[(size_t)k * N + bx * 32 + tx];
    }
    __syncthreads();
    #pragma unroll
    for (int i = 0; i < 4; i++) {
        int nl = ty + i * 8;
        int n  = bx * 32 + nl;
        __half2 v = __floats2half2_rn(t[2 * tx][nl], t[2 * tx + 1][nl]);
        *reinterpret_cast<__half2*>(&T[(size_t)n * K + by * 64 + 2 * tx]) = v;
    }
}

// ---------------- generic fp16 tensor GEMM (small layers) ----------------
template <int ACT>  // 0 = relu, 1 = tanh
__global__ __launch_bounds__(256, 2) void gemmT_h16(
    const __half* __restrict__ A, const __half* __restrict__ Bt,
    const float* __restrict__ bias, __half* __restrict__ C,
    int K, int N, int nch)
{
    extern __shared__ char dynsmem[];
    const uint32_t sbase = smem_u32(dynsmem);

    const int tid  = threadIdx.x;
    const int lane = tid & 31;
    const int wid  = tid >> 5;
    const int wm   = wid & 3;
    const int wn   = wid >> 2;
    const int tile_n = blockIdx.x, tile_m = blockIdx.y;

    auto load_chunk = [&](int stage, int kc) {
        const uint32_t st = sbase + stage * 32768;
        #pragma unroll
        for (int it = 0; it < 8; it++) {
            int u   = tid + it * 256;
            int buf = u >> 10;
            int idx = u & 1023;
            int row = idx >> 3;
            int c   = idx & 7;
            uint32_t dst = st + buf * 16384 + row * 128 + ((c ^ (row & 7)) << 4);
            const __half* src = buf ? Bt : A;
            int grow = (buf ? tile_n : tile_m) * 128 + row;
            cp_async16(dst, (const char*)src + ((size_t)grow * K + kc * 64 + c * 8) * 2);
        }
        CP_COMMIT();
    };

    float acc[2][8][4];
    #pragma unroll
    for (int i = 0; i < 2; i++)
        #pragma unroll
        for (int j = 0; j < 8; j++)
            #pragma unroll
            for (int t = 0; t < 4; t++) acc[i][j][t] = 0.0f;

    load_chunk(0, 0);
    if (nch > 1) load_chunk(1, 1);

    const int a_row_in = (lane & 15);
    const int a_cb_add = (lane >> 4);
    const int b_row_in = ((lane >> 4) << 3) + (lane & 7);
    const int b_cb_add = (lane >> 3) & 1;

    for (int c = 0; c < nch; ++c) {
        if (c < nch - 1) asm volatile("cp.async.wait_group 1;" ::: "memory");
        else             asm volatile("cp.async.wait_group 0;" ::: "memory");
        __syncthreads();
        if (c + 2 < nch) load_chunk((c + 2) % 3, c + 2);

        const uint32_t aB = sbase + (c % 3) * 32768;
        const uint32_t bB = aB + 16384;

        #pragma unroll
        for (int kk = 0; kk < 4; kk++) {
            const int cb = kk * 2;
            uint32_t ah[2][4];
            #pragma unroll
            for (int mi = 0; mi < 2; mi++) {
                int row = wm * 32 + mi * 16 + a_row_in;
                uint32_t off = row * 128 + (((cb + a_cb_add) ^ (row & 7)) << 4);
                ldsm_x4(ah[mi], aB + off);
            }
            uint32_t bh[4][4];
            #pragma unroll
            for (int nq = 0; nq < 4; nq++) {
                int row = wn * 64 + nq * 16 + b_row_in;
                uint32_t off = row * 128 + (((cb + b_cb_add) ^ (row & 7)) << 4);
                ldsm_x4(bh[nq], bB + off);
            }
            #pragma unroll
            for (int nq = 0; nq < 4; nq++)
                #pragma unroll
                for (int mi = 0; mi < 2; mi++) {
                    mma16816h(acc[mi][2 * nq],     ah[mi], bh[nq][0], bh[nq][1]);
                    mma16816h(acc[mi][2 * nq + 1], ah[mi], bh[nq][2], bh[nq][3]);
                }
        }
    }

    const int col0 = tile_n * 128 + wn * 64 + (lane & 3) * 2;
    #pragma unroll
    for (int mi = 0; mi < 2; mi++) {
        int r0 = tile_m * 128 + wm * 32 + mi * 16 + (lane >> 2);
        #pragma unroll
        for (int nb = 0; nb < 8; nb++) {
            int col = col0 + nb * 8;
            float b0 = __ldg(bias + col), b1 = __ldg(bias + col + 1);
            float v0 = acc[mi][nb][0] + b0, v1 = acc[mi][nb][1] + b1;
            float v2 = acc[mi][nb][2] + b0, v3 = acc[mi][nb][3] + b1;
            if (ACT == 0) {
                v0 = fmaxf(v0, 0.f); v1 = fmaxf(v1, 0.f);
                v2 = fmaxf(v2, 0.f); v3 = fmaxf(v3, 0.f);
            } else {
                v0 = tanhf(v0); v1 = tanhf(v1);
                v2 = tanhf(v2); v3 = tanhf(v3);
            }
            *reinterpret_cast<__half2*>(C + (size_t)r0 * N + col) = __floats2half2_rn(v0, v1);
            *reinterpret_cast<__half2*>(C + (size_t)(r0 + 8) * N + col) = __floats2half2_rn(v2, v3);
        }
    }
}

// ---------------- gemm3: dedicated big GEMM, warp tile 64x64 (MMA:ldsm = 4:1) ----
// CTA 128x128, 128 threads (4 warps: 2m x 2n). K=512 in 8 chunks of 64.
// 3-stage ring (96 KB), 2 CTAs/SM.
__global__ __launch_bounds__(128, 2) void gemm3_big(
    const __half* __restrict__ A, const __half* __restrict__ Bt,
    const float* __restrict__ bias, __half* __restrict__ C)
{
    extern __shared__ char dynsmem[];
    const uint32_t sbase = smem_u32(dynsmem);
    constexpr int K = 512, N = 4096, NCH = 8;

    const int tid  = threadIdx.x;
    const int lane = tid & 31;
    const int wid  = tid >> 5;
    const int wm   = wid & 1;          // 2 m-blocks of 64
    const int wn   = wid >> 1;         // 2 n-blocks of 64
    const int tile_n = blockIdx.x, tile_m = blockIdx.y;

    auto load_chunk = [&](int stage, int kc) {
        const uint32_t st = sbase + stage * 32768;
        #pragma unroll
        for (int it = 0; it < 16; it++) {
            int u   = tid + it * 128;
            int buf = u >> 10;
            int idx = u & 1023;
            int row = idx >> 3;
            int c   = idx & 7;
            uint32_t dst = st + buf * 16384 + row * 128 + ((c ^ (row & 7)) << 4);
            const __half* src = buf ? Bt : A;
            int grow = (buf ? tile_n : tile_m) * 128 + row;
            cp_async16(dst, (const char*)src + ((size_t)grow * K + kc * 64 + c * 8) * 2);
        }
        CP_COMMIT();
    };

    float acc[4][8][4];
    #pragma unroll
    for (int i = 0; i < 4; i++)
        #pragma unroll
        for (int j = 0; j < 8; j++)
            #pragma unroll
            for (int t = 0; t < 4; t++) acc[i][j][t] = 0.0f;

    load_chunk(0, 0);
    load_chunk(1, 1);

    const int a_row_in = (lane & 15);
    const int a_cb_add = (lane >> 4);
    const int b_row_in = ((lane >> 4) << 3) + (lane & 7);
    const int b_cb_add = (lane >> 3) & 1;

    for (int c = 0; c < NCH; ++c) {
        if (c < NCH - 1) asm volatile("cp.async.wait_group 1;" ::: "memory");
        else             asm volatile("cp.async.wait_group 0;" ::: "memory");
        __syncthreads();
        if (c + 2 < NCH) load_chunk((c + 2) % 3, c + 2);

        const uint32_t aB = sbase + (c % 3) * 32768;
        const uint32_t bB = aB + 16384;

        #pragma unroll
        for (int kk = 0; kk < 4; kk++) {
            const int cb = kk * 2;
            uint32_t ah[4][4];
            #pragma unroll
            for (int mi = 0; mi < 4; mi++) {
                int row = wm * 64 + mi * 16 + a_row_in;
                uint32_t off = row * 128 + (((cb + a_cb_add) ^ (row & 7)) << 4);
                ldsm_x4(ah[mi], aB + off);
            }
            uint32_t bh[4][4];
            #pragma unroll
            for (int nq = 0; nq < 4; nq++) {
                int row = wn * 64 + nq * 16 + b_row_in;
                uint32_t off = row * 128 + (((cb + b_cb_add) ^ (row & 7)) << 4);
                ldsm_x4(bh[nq], bB + off);
            }
            #pragma unroll
            for (int nq = 0; nq < 4; nq++)
                #pragma unroll
                for (int mi = 0; mi < 4; mi++) {
                    mma16816h(acc[mi][2 * nq],     ah[mi], bh[nq][0], bh[nq][1]);
                    mma16816h(acc[mi][2 * nq + 1], ah[mi], bh[nq][2], bh[nq][3]);
                }
        }
    }

    const int col0 = tile_n * 128 + wn * 64 + (lane & 3) * 2;
    #pragma unroll
    for (int mi = 0; mi < 4; mi++) {
        int r0 = tile_m * 128 + wm * 64 + mi * 16 + (lane >> 2);
        #pragma unroll
        for (int nb = 0; nb < 8; nb++) {
            int col = col0 + nb * 8;
            float b0 = __ldg(bias + col), b1 = __ldg(bias + col + 1);
            __half2 h0 = __floats2half2_rn(tanhf(acc[mi][nb][0] + b0),
                                           tanhf(acc[mi][nb][1] + b1));
            __half2 h1 = __floats2half2_rn(tanhf(acc[mi][nb][2] + b0),
                                           tanhf(acc[mi][nb][3] + b1));
            *reinterpret_cast<__half2*>(C + (size_t)r0 * N + col) = h0;
            *reinterpret_cast<__half2*>(C + (size_t)(r0 + 8) * N + col) = h1;
        }
    }
}

// ---------------- shared conv core (single-sync, register conv) ----------------
__device__ __forceinline__ void conv_and_store(
    const float* __restrict__ img, const float* __restrict__ g,
    float* __restrict__ outc, int tid)
{
    const int r0 = (tid >> 4) << 2;
    const int c0 = (tid & 15) << 2;

    float h[8][4];
    #pragma unroll
    for (int i = 0; i < 8; i++) {
        int r = r0 - 2 + i;
        if (r >= 0 && r < 64) {
            const float* ir = &img[r << 6];
            float x[12];
            if (c0 > 0) {
                float4 v = *reinterpret_cast<const float4*>(ir + c0 - 4);
                x[0] = v.x; x[1] = v.y; x[2] = v.z; x[3] = v.w;
            } else { x[0] = x[1] = x[2] = x[3] = 0.0f; }
            {
                float4 v = *reinterpret_cast<const float4*>(ir + c0);
                x[4] = v.x; x[5] = v.y; x[6] = v.z; x[7] = v.w;
            }
            if (c0 < 60) {
                float4 v = *reinterpret_cast<const float4*>(ir + c0 + 4);
                x[8] = v.x; x[9] = v.y; x[10] = v.z; x[11] = v.w;
            } else { x[8] = x[9] = x[10] = x[11] = 0.0f; }
            #pragma unroll
            for (int j = 0; j < 4; j++)
                h[i][j] = g[0]*x[j+2] + g[1]*x[j+3] + g[2]*x[j+4] + g[3]*x[j+5] + g[4]*x[j+6];
        } else {
            #pragma unroll
            for (int j = 0; j < 4; j++) h[i][j] = 0.0f;
        }
    }

    #pragma unroll
    for (int i = 0; i < 4; i++) {
        float4 o;
        o.x = g[0]*h[i][0] + g[1]*h[i+1][0] + g[2]*h[i+2][0] + g[3]*h[i+3][0] + g[4]*h[i+4][0];
        o.y = g[0]*h[i][1] + g[1]*h[i+1][1] + g[2]*h[i+2][1] + g[3]*h[i+3][1] + g[4]*h[i+4][1];
        o.z = g[0]*h[i][2] + g[1]*h[i+1][2] + g[2]*h[i+2][2] + g[3]*h[i+3][2] + g[4]*h[i+4][2];
        o.w = g[0]*h[i][3] + g[1]*h[i+1][3] + g[2]*h[i+2][3] + g[3]*h[i+3][3] + g[4]*h[i+4][3];
        *reinterpret_cast<float4*>(outc + ((r0 + i) << 6) + c0) = o;
    }
}

__device__ __forceinline__ void gauss5(float* g) {
    float s = 0.0f;
    #pragma unroll
    for (int i = 0; i < 5; i++) {
        float c = (float)(i - 2);
        g[i] = expf(-c * c * 0.5f);
        s += g[i];
    }
    #pragma unroll
    for (int i = 0; i < 5; i++) g[i] /= s;
}

// ---- channel 0 (spatial, needs S) ----
__global__ __launch_bounds__(256) void assemble_ch0(
    const __half* __restrict__ S, float* __restrict__ out)
{
    __shared__ float img[64 * 64];
    const int b = blockIdx.x, tid = threadIdx.x;
    float g[5]; gauss5(g);

    const uint4* S4 = reinterpret_cast<const uint4*>(S + (size_t)b * 4096);
    #pragma unroll
    for (int it = 0; it < 2; it++) {
        int i = tid + it * 256;
        uint4 u = S4[i];
        const __half2* hp = reinterpret_cast<const __half2*>(&u);
        float* d = &img[i << 3];
        #pragma unroll
        for (int j = 0; j < 4; j++) {
            float2 f = __half22float2(hp[j]);
            d[2 * j] = f.x; d[2 * j + 1] = f.y;
        }
    }
    __syncthreads();
    conv_and_store(img, g, out + (size_t)b * 3 * 4096, tid);
}

// ---- channels 1,2 (freq/block; independent of S) ----
__global__ __launch_bounds__(256) void assemble_ch12(
    const __half* __restrict__ FL, const float* __restrict__ msg,
    float* __restrict__ out)
{
    __shared__ float img[64 * 64];
    __shared__ float fl[256];
    const int b = blockIdx.x, ch = blockIdx.y + 1, tid = threadIdx.x;
    float g[5]; gauss5(g);

    if (ch == 1) {
        fl[tid] = __half2float(FL[(size_t)b * 256 + tid]);
        __syncthreads();
        #pragma unroll
        for (int it = 0; it < 16; it++) {
            int idx = tid + it * 256;
            int p = idx >> 6, q = idx & 63;
            float pp = (float)(p * 15) / 63.0f;
            float pq = (float)(q * 15) / 63.0f;
            int lp = (int)pp, lq = (int)pq;
            float wp = pp - (float)lp, wq = pq - (float)lq;
            int hp = min(lp + 1, 15), hq = min(lq + 1, 15);
            float v00 = fl[lp * 16 + lq], v01 = fl[lp * 16 + hq];
            float v10 = fl[hp * 16 + lq], v11 = fl[hp * 16 + hq];
            float top = (1.0f - wq) * v00 + wq * v01;
            float bot = (1.0f - wq) * v10 + wq * v11;
            img[idx] = (1.0f - wp) * top + wp * bot;
        }
    } else {
        if (tid < 64) fl[tid] = msg[(size_t)b * 64 + tid];
        __syncthreads();
        #pragma unroll
        for (int it = 0; it < 16; it++) {
            int idx = tid + it * 256;
            int p = idx >> 6, q = idx & 63;
            img[idx] = fl[((p >> 3) << 3) + (q >> 3)];
        }
    }
    __syncthreads();
    conv_and_store(img, g, out + ((size_t)b * 3 + ch) * 4096, tid);
}

// ---------------- launch (R13 fork-join structure) ----------------
extern "C" void kernel_launch(void* const* d_in, const int* in_sizes, int n_in,
                              void* d_out, int out_size)
{
    const float* msg = (const float*)d_in[0];
    const float* sW1 = (const float*)d_in[1];
    const float* sb1 = (const float*)d_in[2];
    const float* sW2 = (const float*)d_in[3];
    const float* sb2 = (const float*)d_in[4];
    const float* sW3 = (const float*)d_in[5];
    const float* sb3 = (const float*)d_in[6];
    const float* fW1 = (const float*)d_in[7];
    const float* fb1 = (const float*)d_in[8];
    const float* fW2 = (const float*)d_in[9];
    const float* fb2 = (const float*)d_in[10];
    float* out = (float*)d_out;

    __half *msgh, *w1t, *w2t, *w3t, *fw1t, *fw2t, *h1, *h2, *S, *f, *FL;
    cudaGetSymbolAddress((void**)&msgh, g_msgh);
    cudaGetSymbolAddress((void**)&w1t,  g_w1t);
    cudaGetSymbolAddress((void**)&w2t,  g_w2t);
    cudaGetSymbolAddress((void**)&w3t,  g_w3t);
    cudaGetSymbolAddress((void**)&fw1t, g_fw1t);
    cudaGetSymbolAddress((void**)&fw2t, g_fw2t);
    cudaGetSymbolAddress((void**)&h1,   g_h1);
    cudaGetSymbolAddress((void**)&h2,   g_h2);
    cudaGetSymbolAddress((void**)&S,    g_S);
    cudaGetSymbolAddress((void**)&f,    g_f);
    cudaGetSymbolAddress((void**)&FL,   g_FL);

    cudaFuncSetAttribute(gemmT_h16<0>, cudaFuncAttributeMaxDynamicSharedMemorySize, 98304);
    cudaFuncSetAttribute(gemmT_h16<1>, cudaFuncAttributeMaxDynamicSharedMemorySize, 98304);
    cudaFuncSetAttribute(gemm3_big,    cudaFuncAttributeMaxDynamicSharedMemorySize, 98304);

    static cudaStream_t s1 = nullptr, s2 = nullptr;
    static cudaEvent_t evFork = nullptr, ev1 = nullptr, ev2 = nullptr;
    if (s1 == nullptr) {
        cudaStreamCreateWithFlags(&s1, cudaStreamNonBlocking);
        cudaStreamCreateWithFlags(&s2, cudaStreamNonBlocking);
        cudaEventCreateWithFlags(&evFork, cudaEventDisableTiming);
        cudaEventCreateWithFlags(&ev1, cudaEventDisableTiming);
        cudaEventCreateWithFlags(&ev2, cudaEventDisableTiming);
    }

    // main stream: msg -> fp16 (needed by both chains)
    f32_to_f16<<<4096 * 64 / 512, 256>>>(msg, msgh);
    cudaEventRecord(evFork, 0);
    cudaStreamWaitEvent(s1, evFork, 0);
    cudaStreamWaitEvent(s2, evFork, 0);

    // s1: big weight transpose (overlaps gemm1/gemm2)
    transpose_h16<<<dim3(4096 / 32, 512 / 64), dim3(32, 8), 0, s1>>>(sW3, w3t, 512, 4096);
    cudaEventRecord(ev1, s1);

    // s2: freq chain + channels 1,2 of output (independent of S)
    transpose_h16<<<dim3(128 / 32, 64 / 64),  dim3(32, 8), 0, s2>>>(fW1, fw1t, 64, 128);
    transpose_h16<<<dim3(256 / 32, 128 / 64), dim3(32, 8), 0, s2>>>(fW2, fw2t, 128, 256);
    gemmT_h16<0><<<dim3(1, 32), 256, 98304, s2>>>(msgh, fw1t, fb1, f,  64, 128, 1);
    gemmT_h16<1><<<dim3(2, 32), 256, 98304, s2>>>(f,    fw2t, fb2, FL, 128, 256, 2);
    assemble_ch12<<<dim3(4096, 2), 256, 0, s2>>>(FL, msg, out);
    cudaEventRecord(ev2, s2);

    // main stream: spatial chain
    transpose_h16<<<dim3(256 / 32, 64 / 64),  dim3(32, 8)>>>(sW1, w1t, 64, 256);
    transpose_h16<<<dim3(512 / 32, 256 / 64), dim3(32, 8)>>>(sW2, w2t, 256, 512);
    gemmT_h16<0><<<dim3(2, 32), 256, 98304>>>(msgh, w1t, sb1, h1, 64, 256, 1);
    gemmT_h16<0><<<dim3(4, 32), 256, 98304>>>(h1,   w2t, sb2, h2, 256, 512, 4);
    cudaStreamWaitEvent(0, ev1, 0);
    gemm3_big<<<dim3(32, 32), 128, 98304>>>(h2, w3t, sb3, S);
    assemble_ch0<<<4096, 256>>>(S, out);
    cudaStreamWaitEvent(0, ev2, 0);
}

// round 16
// speedup vs baseline: 1.1421x; 1.0348x over previous
#include <cuda_runtime.h>
#include <cuda_fp16.h>
#include <math.h>
#include <stdint.h>

// ---------------- scratch (static device globals; no allocation) ----------------
__device__ __half  g_msgh[4096 * 64];
__device__ __half  g_w1t [256 * 64];
__device__ __half  g_w2t [512 * 256];
__device__ __half  g_w3t [4096 * 512];
__device__ __half  g_fw1t[128 * 64];
__device__ __half  g_fw2t[256 * 128];
__device__ __half  g_h1  [4096 * 256];
__device__ __half  g_h2  [4096 * 512];
__device__ __half  g_S   [4096u * 4096u];
__device__ __half  g_f   [4096 * 128];
__device__ __half  g_FL  [4096 * 256];

// ---------------- helpers ----------------
__device__ __forceinline__ uint32_t smem_u32(const void* p) {
    uint32_t a;
    asm("{ .reg .u64 t; cvta.to.shared.u64 t, %1; cvt.u32.u64 %0, t; }" : "=r"(a) : "l"(p));
    return a;
}
__device__ __forceinline__ void cp_async16(uint32_t dst, const void* src) {
    asm volatile("cp.async.cg.shared.global [%0], [%1], 16;" :: "r"(dst), "l"(src));
}
#define CP_COMMIT() asm volatile("cp.async.commit_group;" ::: "memory")

__device__ __forceinline__ void ldsm_x4(uint32_t (&r)[4], uint32_t addr) {
    asm volatile("ldmatrix.sync.aligned.m8n8.x4.shared.b16 {%0,%1,%2,%3}, [%4];"
                 : "=r"(r[0]), "=r"(r[1]), "=r"(r[2]), "=r"(r[3]) : "r"(addr));
}
__device__ __forceinline__ void mma16816h(float (&d)[4], const uint32_t (&a)[4],
                                          uint32_t b0, uint32_t b1) {
    asm volatile(
        "mma.sync.aligned.m16n8k16.row.col.f32.f16.f16.f32 "
        "{%0,%1,%2,%3}, {%4,%5,%6,%7}, {%8,%9}, {%0,%1,%2,%3};"
        : "+f"(d[0]), "+f"(d[1]), "+f"(d[2]), "+f"(d[3])
        : "r"(a[0]), "r"(a[1]), "r"(a[2]), "r"(a[3]), "r"(b0), "r"(b1));
}
__device__ __forceinline__ void st_cs_f4(float* p, float4 v) {
    asm volatile("st.global.cs.v4.f32 [%0], {%1,%2,%3,%4};"
                 :: "l"(p), "f"(v.x), "f"(v.y), "f"(v.z), "f"(v.w) : "memory");
}
__device__ __forceinline__ uint4 ld_cs_u4(const uint4* p) {
    uint4 v;
    asm volatile("ld.global.cs.v4.u32 {%0,%1,%2,%3}, [%4];"
                 : "=r"(v.x), "=r"(v.y), "=r"(v.z), "=r"(v.w) : "l"(p));
    return v;
}

// ---------------- fp32 -> fp16 elementwise ----------------
__global__ __launch_bounds__(256) void f32_to_f16(
    const float* __restrict__ x, __half* __restrict__ y)
{
    int i = blockIdx.x * 256 + threadIdx.x;
    float2 v = reinterpret_cast<const float2*>(x)[i];
    reinterpret_cast<__half2*>(y)[i] = __floats2half2_rn(v.x, v.y);
}

// W [K,N] f32 -> W^T fp16 [N,K]
__global__ __launch_bounds__(256) void transpose_h16(
    const float* __restrict__ W, __half* __restrict__ T, int K, int N)
{
    __shared__ float t[64][33];
    int tx = threadIdx.x, ty = threadIdx.y;
    int bx = blockIdx.x, by = blockIdx.y;
    #pragma unroll
    for (int i = 0; i < 8; i++) {
        int k = by * 64 + ty + i * 8;
        t[ty + i * 8][tx] = W[(size_t)k * N + bx * 32 + tx];
    }
    __syncthreads();
    #pragma unroll
    for (int i = 0; i < 4; i++) {
        int nl = ty + i * 8;
        int n  = bx * 32 + nl;
        __half2 v = __floats2half2_rn(t[2 * tx][nl], t[2 * tx + 1][nl]);
        *reinterpret_cast<__half2*>(&T[(size_t)n * K + by * 64 + 2 * tx]) = v;
    }
}

// ---------------- generic fp16 tensor GEMM (small layers) ----------------
template <int ACT>
__global__ __launch_bounds__(256, 2) void gemmT_h16(
    const __half* __restrict__ A, const __half* __restrict__ Bt,
    const float* __restrict__ bias, __half* __restrict__ C,
    int K, int N, int nch)
{
    extern __shared__ char dynsmem[];
    const uint32_t sbase = smem_u32(dynsmem);

    const int tid  = threadIdx.x;
    const int lane = tid & 31;
    const int wid  = tid >> 5;
    const int wm   = wid & 3;
    const int wn   = wid >> 2;
    const int tile_n = blockIdx.x, tile_m = blockIdx.y;

    auto load_chunk = [&](int stage, int kc) {
        const uint32_t st = sbase + stage * 32768;
        #pragma unroll
        for (int it = 0; it < 8; it++) {
            int u   = tid + it * 256;
            int buf = u >> 10;
            int idx = u & 1023;
            int row = idx >> 3;
            int c   = idx & 7;
            uint32_t dst = st + buf * 16384 + row * 128 + ((c ^ (row & 7)) << 4);
            const __half* src = buf ? Bt : A;
            int grow = (buf ? tile_n : tile_m) * 128 + row;
            cp_async16(dst, (const char*)src + ((size_t)grow * K + kc * 64 + c * 8) * 2);
        }
        CP_COMMIT();
    };

    float acc[2][8][4];
    #pragma unroll
    for (int i = 0; i < 2; i++)
        #pragma unroll
        for (int j = 0; j < 8; j++)
            #pragma unroll
            for (int t = 0; t < 4; t++) acc[i][j][t] = 0.0f;

    load_chunk(0, 0);
    if (nch > 1) load_chunk(1, 1);

    const int a_row_in = (lane & 15);
    const int a_cb_add = (lane >> 4);
    const int b_row_in = ((lane >> 4) << 3) + (lane & 7);
    const int b_cb_add = (lane >> 3) & 1;

    for (int c = 0; c < nch; ++c) {
        if (c < nch - 1) asm volatile("cp.async.wait_group 1;" ::: "memory");
        else             asm volatile("cp.async.wait_group 0;" ::: "memory");
        __syncthreads();
        if (c + 2 < nch) load_chunk((c + 2) % 3, c + 2);

        const uint32_t aB = sbase + (c % 3) * 32768;
        const uint32_t bB = aB + 16384;

        #pragma unroll
        for (int kk = 0; kk < 4; kk++) {
            const int cb = kk * 2;
            uint32_t ah[2][4];
            #pragma unroll
            for (int mi = 0; mi < 2; mi++) {
                int row = wm * 32 + mi * 16 + a_row_in;
                uint32_t off = row * 128 + (((cb + a_cb_add) ^ (row & 7)) << 4);
                ldsm_x4(ah[mi], aB + off);
            }
            uint32_t bh[4][4];
            #pragma unroll
            for (int nq = 0; nq < 4; nq++) {
                int row = wn * 64 + nq * 16 + b_row_in;
                uint32_t off = row * 128 + (((cb + b_cb_add) ^ (row & 7)) << 4);
                ldsm_x4(bh[nq], bB + off);
            }
            #pragma unroll
            for (int nq = 0; nq < 4; nq++)
                #pragma unroll
                for (int mi = 0; mi < 2; mi++) {
                    mma16816h(acc[mi][2 * nq],     ah[mi], bh[nq][0], bh[nq][1]);
                    mma16816h(acc[mi][2 * nq + 1], ah[mi], bh[nq][2], bh[nq][3]);
                }
        }
    }

    const int col0 = tile_n * 128 + wn * 64 + (lane & 3) * 2;
    #pragma unroll
    for (int mi = 0; mi < 2; mi++) {
        int r0 = tile_m * 128 + wm * 32 + mi * 16 + (lane >> 2);
        #pragma unroll
        for (int nb = 0; nb < 8; nb++) {
            int col = col0 + nb * 8;
            float b0 = __ldg(bias + col), b1 = __ldg(bias + col + 1);
            float v0 = acc[mi][nb][0] + b0, v1 = acc[mi][nb][1] + b1;
            float v2 = acc[mi][nb][2] + b0, v3 = acc[mi][nb][3] + b1;
            if (ACT == 0) {
                v0 = fmaxf(v0, 0.f); v1 = fmaxf(v1, 0.f);
                v2 = fmaxf(v2, 0.f); v3 = fmaxf(v3, 0.f);
            } else {
                v0 = tanhf(v0); v1 = tanhf(v1);
                v2 = tanhf(v2); v3 = tanhf(v3);
            }
            *reinterpret_cast<__half2*>(C + (size_t)r0 * N + col) = __floats2half2_rn(v0, v1);
            *reinterpret_cast<__half2*>(C + (size_t)(r0 + 8) * N + col) = __floats2half2_rn(v2, v3);
        }
    }
}

// ---------------- gemm3: dedicated big GEMM, warp tile 64x64 ----------------
// CTA 128x128, 128 threads (4 warps: 2m x 2n). m_off = tile_m slab offset.
__global__ __launch_bounds__(128, 2) void gemm3_big(
    const __half* __restrict__ A, const __half* __restrict__ Bt,
    const float* __restrict__ bias, __half* __restrict__ C, int m_off)
{
    extern __shared__ char dynsmem[];
    const uint32_t sbase = smem_u32(dynsmem);
    constexpr int K = 512, N = 4096, NCH = 8;

    const int tid  = threadIdx.x;
    const int lane = tid & 31;
    const int wid  = tid >> 5;
    const int wm   = wid & 1;
    const int wn   = wid >> 1;
    const int tile_n = blockIdx.x, tile_m = blockIdx.y + m_off;

    auto load_chunk = [&](int stage, int kc) {
        const uint32_t st = sbase + stage * 32768;
        #pragma unroll
        for (int it = 0; it < 16; it++) {
            int u   = tid + it * 128;
            int buf = u >> 10;
            int idx = u & 1023;
            int row = idx >> 3;
            int c   = idx & 7;
            uint32_t dst = st + buf * 16384 + row * 128 + ((c ^ (row & 7)) << 4);
            const __half* src = buf ? Bt : A;
            int grow = (buf ? tile_n : tile_m) * 128 + row;
            cp_async16(dst, (const char*)src + ((size_t)grow * K + kc * 64 + c * 8) * 2);
        }
        CP_COMMIT();
    };

    float acc[4][8][4];
    #pragma unroll
    for (int i = 0; i < 4; i++)
        #pragma unroll
        for (int j = 0; j < 8; j++)
            #pragma unroll
            for (int t = 0; t < 4; t++) acc[i][j][t] = 0.0f;

    load_chunk(0, 0);
    load_chunk(1, 1);

    const int a_row_in = (lane & 15);
    const int a_cb_add = (lane >> 4);
    const int b_row_in = ((lane >> 4) << 3) + (lane & 7);
    const int b_cb_add = (lane >> 3) & 1;

    for (int c = 0; c < NCH; ++c) {
        if (c < NCH - 1) asm volatile("cp.async.wait_group 1;" ::: "memory");
        else             asm volatile("cp.async.wait_group 0;" ::: "memory");
        __syncthreads();
        if (c + 2 < NCH) load_chunk((c + 2) % 3, c + 2);

        const uint32_t aB = sbase + (c % 3) * 32768;
        const uint32_t bB = aB + 16384;

        #pragma unroll
        for (int kk = 0; kk < 4; kk++) {
            const int cb = kk * 2;
            uint32_t ah[4][4];
            #pragma unroll
            for (int mi = 0; mi < 4; mi++) {
                int row = wm * 64 + mi * 16 + a_row_in;
                uint32_t off = row * 128 + (((cb + a_cb_add) ^ (row & 7)) << 4);
                ldsm_x4(ah[mi], aB + off);
            }
            uint32_t bh[4][4];
            #pragma unroll
            for (int nq = 0; nq < 4; nq++) {
                int row = wn * 64 + nq * 16 + b_row_in;
                uint32_t off = row * 128 + (((cb + b_cb_add) ^ (row & 7)) << 4);
                ldsm_x4(bh[nq], bB + off);
            }
            #pragma unroll
            for (int nq = 0; nq < 4; nq++)
                #pragma unroll
                for (int mi = 0; mi < 4; mi++) {
                    mma16816h(acc[mi][2 * nq],     ah[mi], bh[nq][0], bh[nq][1]);
                    mma16816h(acc[mi][2 * nq + 1], ah[mi], bh[nq][2], bh[nq][3]);
                }
        }
    }

    const int col0 = tile_n * 128 + wn * 64 + (lane & 3) * 2;
    #pragma unroll
    for (int mi = 0; mi < 4; mi++) {
        int r0 = tile_m * 128 + wm * 64 + mi * 16 + (lane >> 2);
        #pragma unroll
        for (int nb = 0; nb < 8; nb++) {
            int col = col0 + nb * 8;
            float b0 = __ldg(bias + col), b1 = __ldg(bias + col + 1);
            __half2 h0 = __floats2half2_rn(tanhf(acc[mi][nb][0] + b0),
                                           tanhf(acc[mi][nb][1] + b1));
            __half2 h1 = __floats2half2_rn(tanhf(acc[mi][nb][2] + b0),
                                           tanhf(acc[mi][nb][3] + b1));
            *reinterpret_cast<__half2*>(C + (size_t)r0 * N + col) = h0;
            *reinterpret_cast<__half2*>(C + (size_t)(r0 + 8) * N + col) = h1;
        }
    }
}

// ---------------- shared conv core (single-sync; streaming stores) ----------------
__device__ __forceinline__ void conv_and_store(
    const float* __restrict__ img, const float* __restrict__ g,
    float* __restrict__ outc, int tid)
{
    const int r0 = (tid >> 4) << 2;
    const int c0 = (tid & 15) << 2;

    float h[8][4];
    #pragma unroll
    for (int i = 0; i < 8; i++) {
        int r = r0 - 2 + i;
        if (r >= 0 && r < 64) {
            const float* ir = &img[r << 6];
            float x[12];
            if (c0 > 0) {
                float4 v = *reinterpret_cast<const float4*>(ir + c0 - 4);
                x[0] = v.x; x[1] = v.y; x[2] = v.z; x[3] = v.w;
            } else { x[0] = x[1] = x[2] = x[3] = 0.0f; }
            {
                float4 v = *reinterpret_cast<const float4*>(ir + c0);
                x[4] = v.x; x[5] = v.y; x[6] = v.z; x[7] = v.w;
            }
            if (c0 < 60) {
                float4 v = *reinterpret_cast<const float4*>(ir + c0 + 4);
                x[8] = v.x; x[9] = v.y; x[10] = v.z; x[11] = v.w;
            } else { x[8] = x[9] = x[10] = x[11] = 0.0f; }
            #pragma unroll
            for (int j = 0; j < 4; j++)
                h[i][j] = g[0]*x[j+2] + g[1]*x[j+3] + g[2]*x[j+4] + g[3]*x[j+5] + g[4]*x[j+6];
        } else {
            #pragma unroll
            for (int j = 0; j < 4; j++) h[i][j] = 0.0f;
        }
    }

    #pragma unroll
    for (int i = 0; i < 4; i++) {
        float4 o;
        o.x = g[0]*h[i][0] + g[1]*h[i+1][0] + g[2]*h[i+2][0] + g[3]*h[i+3][0] + g[4]*h[i+4][0];
        o.y = g[0]*h[i][1] + g[1]*h[i+1][1] + g[2]*h[i+2][1] + g[3]*h[i+3][1] + g[4]*h[i+4][1];
        o.z = g[0]*h[i][2] + g[1]*h[i+1][2] + g[2]*h[i+2][2] + g[3]*h[i+3][2] + g[4]*h[i+4][2];
        o.w = g[0]*h[i][3] + g[1]*h[i+1][3] + g[2]*h[i+2][3] + g[3]*h[i+3][3] + g[4]*h[i+4][3];
        st_cs_f4(outc + ((r0 + i) << 6) + c0, o);
    }
}

__device__ __forceinline__ void gauss5(float* g) {
    float s = 0.0f;
    #pragma unroll
    for (int i = 0; i < 5; i++) {
        float c = (float)(i - 2);
        g[i] = expf(-c * c * 0.5f);
        s += g[i];
    }
    #pragma unroll
    for (int i = 0; i < 5; i++) g[i] /= s;
}

// ---- channel 0 (spatial, needs S); b_off = batch slab offset ----
__global__ __launch_bounds__(256) void assemble_ch0(
    const __half* __restrict__ S, float* __restrict__ out, int b_off)
{
    __shared__ float img[64 * 64];
    const int b = blockIdx.x + b_off, tid = threadIdx.x;
    float g[5]; gauss5(g);

    const uint4* S4 = reinterpret_cast<const uint4*>(S + (size_t)b * 4096);
    #pragma unroll
    for (int it = 0; it < 2; it++) {
        int i = tid + it * 256;
        uint4 u = ld_cs_u4(S4 + i);
        const __half2* hp = reinterpret_cast<const __half2*>(&u);
        float* d = &img[i << 3];
        #pragma unroll
        for (int j = 0; j < 4; j++) {
            float2 f = __half22float2(hp[j]);
            d[2 * j] = f.x; d[2 * j + 1] = f.y;
        }
    }
    __syncthreads();
    conv_and_store(img, g, out + (size_t)b * 3 * 4096, tid);
}

// ---- channels 1,2 (freq/block; independent of S) ----
__global__ __launch_bounds__(256) void assemble_ch12(
    const __half* __restrict__ FL, const float* __restrict__ msg,
    float* __restrict__ out)
{
    __shared__ float img[64 * 64];
    __shared__ float fl[256];
    const int b = blockIdx.x, ch = blockIdx.y + 1, tid = threadIdx.x;
    float g[5]; gauss5(g);

    if (ch == 1) {
        fl[tid] = __half2float(FL[(size_t)b * 256 + tid]);
        __syncthreads();
        #pragma unroll
        for (int it = 0; it < 16; it++) {
            int idx = tid + it * 256;
            int p = idx >> 6, q = idx & 63;
            float pp = (float)(p * 15) / 63.0f;
            float pq = (float)(q * 15) / 63.0f;
            int lp = (int)pp, lq = (int)pq;
            float wp = pp - (float)lp, wq = pq - (float)lq;
            int hp = min(lp + 1, 15), hq = min(lq + 1, 15);
            float v00 = fl[lp * 16 + lq], v01 = fl[lp * 16 + hq];
            float v10 = fl[hp * 16 + lq], v11 = fl[hp * 16 + hq];
            float top = (1.0f - wq) * v00 + wq * v01;
            float bot = (1.0f - wq) * v10 + wq * v11;
            img[idx] = (1.0f - wp) * top + wp * bot;
        }
    } else {
        if (tid < 64) fl[tid] = msg[(size_t)b * 64 + tid];
        __syncthreads();
        #pragma unroll
        for (int it = 0; it < 16; it++) {
            int idx = tid + it * 256;
            int p = idx >> 6, q = idx & 63;
            img[idx] = fl[((p >> 3) << 3) + (q >> 3)];
        }
    }
    __syncthreads();
    conv_and_store(img, g, out + ((size_t)b * 3 + ch) * 4096, tid);
}

// ---------------- launch (fork-join + 2-slab gemm3/ch0 pipeline) ----------------
extern "C" void kernel_launch(void* const* d_in, const int* in_sizes, int n_in,
                              void* d_out, int out_size)
{
    const float* msg = (const float*)d_in[0];
    const float* sW1 = (const float*)d_in[1];
    const float* sb1 = (const float*)d_in[2];
    const float* sW2 = (const float*)d_in[3];
    const float* sb2 = (const float*)d_in[4];
    const float* sW3 = (const float*)d_in[5];
    const float* sb3 = (const float*)d_in[6];
    const float* fW1 = (const float*)d_in[7];
    const float* fb1 = (const float*)d_in[8];
    const float* fW2 = (const float*)d_in[9];
    const float* fb2 = (const float*)d_in[10];
    float* out = (float*)d_out;

    __half *msgh, *w1t, *w2t, *w3t, *fw1t, *fw2t, *h1, *h2, *S, *f, *FL;
    cudaGetSymbolAddress((void**)&msgh, g_msgh);
    cudaGetSymbolAddress((void**)&w1t,  g_w1t);
    cudaGetSymbolAddress((void**)&w2t,  g_w2t);
    cudaGetSymbolAddress((void**)&w3t,  g_w3t);
    cudaGetSymbolAddress((void**)&fw1t, g_fw1t);
    cudaGetSymbolAddress((void**)&fw2t, g_fw2t);
    cudaGetSymbolAddress((void**)&h1,   g_h1);
    cudaGetSymbolAddress((void**)&h2,   g_h2);
    cudaGetSymbolAddress((void**)&S,    g_S);
    cudaGetSymbolAddress((void**)&f,    g_f);
    cudaGetSymbolAddress((void**)&FL,   g_FL);

    cudaFuncSetAttribute(gemmT_h16<0>, cudaFuncAttributeMaxDynamicSharedMemorySize, 98304);
    cudaFuncSetAttribute(gemmT_h16<1>, cudaFuncAttributeMaxDynamicSharedMemorySize, 98304);
    cudaFuncSetAttribute(gemm3_big,    cudaFuncAttributeMaxDynamicSharedMemorySize, 98304);

    static cudaStream_t s1 = nullptr, s2 = nullptr, s3 = nullptr;
    static cudaEvent_t evFork = nullptr, ev1 = nullptr, ev2 = nullptr, ev3 = nullptr,
                       evSlab0 = nullptr, evSlab1 = nullptr;
    if (s1 == nullptr) {
        cudaStreamCreateWithFlags(&s1, cudaStreamNonBlocking);
        cudaStreamCreateWithFlags(&s2, cudaStreamNonBlocking);
        cudaStreamCreateWithFlags(&s3, cudaStreamNonBlocking);
        cudaEventCreateWithFlags(&evFork, cudaEventDisableTiming);
        cudaEventCreateWithFlags(&ev1, cudaEventDisableTiming);
        cudaEventCreateWithFlags(&ev2, cudaEventDisableTiming);
        cudaEventCreateWithFlags(&ev3, cudaEventDisableTiming);
        cudaEventCreateWithFlags(&evSlab0, cudaEventDisableTiming);
        cudaEventCreateWithFlags(&evSlab1, cudaEventDisableTiming);
    }

    // main: msg convert; fork
    f32_to_f16<<<4096 * 64 / 512, 256>>>(msg, msgh);
    cudaEventRecord(evFork, 0);
    cudaStreamWaitEvent(s1, evFork, 0);
    cudaStreamWaitEvent(s2, evFork, 0);

    // s1: big weight transpose (overlaps gemm1/gemm2)
    transpose_h16<<<dim3(4096 / 32, 512 / 64), dim3(32, 8), 0, s1>>>(sW3, w3t, 512, 4096);
    cudaEventRecord(ev1, s1);

    // s2: freq chain + channels 1,2 (independent of S)
    transpose_h16<<<dim3(128 / 32, 64 / 64),  dim3(32, 8), 0, s2>>>(fW1, fw1t, 64, 128);
    transpose_h16<<<dim3(256 / 32, 128 / 64), dim3(32, 8), 0, s2>>>(fW2, fw2t, 128, 256);
    gemmT_h16<0><<<dim3(1, 32), 256, 98304, s2>>>(msgh, fw1t, fb1, f,  64, 128, 1);
    gemmT_h16<1><<<dim3(2, 32), 256, 98304, s2>>>(f,    fw2t, fb2, FL, 128, 256, 2);
    assemble_ch12<<<dim3(4096, 2), 256, 0, s2>>>(FL, msg, out);
    cudaEventRecord(ev2, s2);

    // main: spatial chain
    transpose_h16<<<dim3(256 / 32, 64 / 64),  dim3(32, 8)>>>(sW1, w1t, 64, 256);
    transpose_h16<<<dim3(512 / 32, 256 / 64), dim3(32, 8)>>>(sW2, w2t, 256, 512);
    gemmT_h16<0><<<dim3(2, 32), 256, 98304>>>(msgh, w1t, sb1, h1, 64, 256, 1);
    gemmT_h16<0><<<dim3(4, 32), 256, 98304>>>(h1,   w2t, sb2, h2, 256, 512, 4);
    cudaStreamWaitEvent(0, ev1, 0);

    // gemm3 in 2 slabs; ch0 pipelined on s3
    gemm3_big<<<dim3(32, 16), 128, 98304>>>(h2, w3t, sb3, S, 0);
    cudaEventRecord(evSlab0, 0);
    gemm3_big<<<dim3(32, 16), 128, 98304>>>(h2, w3t, sb3, S, 16);
    cudaEventRecord(evSlab1, 0);

    cudaStreamWaitEvent(s3, evSlab0, 0);
    assemble_ch0<<<2048, 256, 0, s3>>>(S, out, 0);
    cudaStreamWaitEvent(s3, evSlab1, 0);
    assemble_ch0<<<2048, 256, 0, s3>>>(S, out, 2048);
    cudaEventRecord(ev3, s3);

    // join
    cudaStreamWaitEvent(0, ev2, 0);
    cudaStreamWaitEvent(0, ev3, 0);
}